// round 13
// baseline (speedup 1.0000x reference)
#include <cuda_runtime.h>
#include <cuda_fp16.h>
#include <math.h>

#define N_NODESC 20000
#define WINDOWC  8
#define N_BIGC   160000
#define IN_CC    8
#define HIDC     64
#define E_MAIN   1600000
#define E_DECC   500000
#define DHC      143
#define PSTRIDE  144

typedef unsigned long long u64;

// ---------------- scratch (static device globals; no allocation) ----------------
__device__ float g_dis[N_BIGC];
__device__ float g_h[N_BIGC * HIDC];          // GCN2 GEMM output
__device__ float g_Xc[N_BIGC * 2 * HIDC];     // pre-BN relu outputs of both layers
__device__ float g_gates[N_BIGC * 4 * HIDC];  // fp32 gate preactivations
__device__ float g_y1[N_BIGC * HIDC];
__device__ float g_emb[N_NODESC * DHC];       // H1 | H2 | S (filled by lstm1/lstm2/embS)
__device__ __half g_Psh[N_NODESC * PSTRIDE];  // col 143 never written -> stays 0
__device__ __half g_Pth[N_NODESC * PSTRIDE];
__device__ float g_stats[128];
__device__ float g_bnp12[256];                // scale[128], shift[128] for Xc columns
// CSR (built once per launch, used by both GCN layers)
__device__ int2  g_csr[E_MAIN];
__device__ int   g_cnt[N_BIGC];
__device__ int   g_off[N_BIGC];
__device__ int   g_cur[N_BIGC];
__device__ int   g_total[1];

// ---------------- packed f32x2 helpers ----------------
__device__ __forceinline__ u64 fma2(u64 a, u64 b, u64 c) {
    u64 d;
    asm("fma.rn.f32x2 %0, %1, %2, %3;" : "=l"(d) : "l"(a), "l"(b), "l"(c));
    return d;
}
__device__ __forceinline__ u64 pack2(float lo, float hi) {
    u64 p;
    asm("mov.b64 %0, {%1, %2};" : "=l"(p) : "f"(lo), "f"(hi));
    return p;
}
__device__ __forceinline__ float sum2(u64 p) {
    float lo, hi;
    asm("mov.b64 {%0, %1}, %2;" : "=f"(lo), "=f"(hi) : "l"(p));
    return lo + hi;
}

// ---------------- init ----------------
__global__ void k_init() {
    int i = blockIdx.x * blockDim.x + threadIdx.x;
    if (i < N_BIGC) { g_dis[i] = 0.f; g_cnt[i] = 0; }
    if (i < 128) g_stats[i] = 0.f;
    if (i == 0) g_total[0] = 0;
}

// skip features S -> emb cols 128..142 (depends only on x; launched early)
__global__ void k_embS(const float* __restrict__ x) {
    int i = blockIdx.x * blockDim.x + threadIdx.x;
    if (i >= N_NODESC * 15) return;
    int b = i / 15, j = i - b * 15;
    float v;
    if (j < 8) v = x[(size_t)b * 8 + j];
    else { int t = j - 7; v = x[((size_t)t * N_NODESC + b) * 8 + 7]; }
    g_emb[(size_t)b * DHC + 128 + j] = v;
}

__global__ void k_degcount(const int* __restrict__ ei, const float* __restrict__ ea) {
    int i = blockIdx.x * blockDim.x + threadIdx.x;
    if (i < E_MAIN) {
        int c = ei[E_MAIN + i];
        atomicAdd(&g_dis[c], ea[i]);
        atomicAdd(&g_cnt[c], 1);
    }
}

__global__ void k_disalloc() {
    int i = blockIdx.x * blockDim.x + threadIdx.x;
    if (i >= N_BIGC) return;
    g_dis[i] = rsqrtf(g_dis[i] + 1.0f);
    int lane = threadIdx.x & 31;
    int c = g_cnt[i];
    int scan = c;
#pragma unroll
    for (int o = 1; o < 32; o <<= 1) {
        int v = __shfl_up_sync(0xffffffffu, scan, o);
        if (lane >= o) scan += v;
    }
    int excl = scan - c;
    int base = 0;
    if (lane == 31) base = atomicAdd(&g_total[0], scan);
    base = __shfl_sync(0xffffffffu, base, 31);
    g_off[i] = base + excl;
    g_cur[i] = base + excl;
}

__global__ void k_fill(const int* __restrict__ ei, const float* __restrict__ ea) {
    int e = blockIdx.x * blockDim.x + threadIdx.x;
    if (e >= E_MAIN) return;
    int r = ei[e], c = ei[E_MAIN + e];
    float w = g_dis[r] * ea[e] * g_dis[c];
    int pos = atomicAdd(&g_cur[c], 1);
    g_csr[pos] = make_int2(r, __float_as_int(w));
}

// ---------------- fused layer-1: aggregate raw x + @W1 + b1 + relu + stats ----------------
// 8 lanes per node (c = lane&7), 4 nodes per warp, 32 nodes per block; grid 5000
__global__ void __launch_bounds__(256)
k_gcn1(const float* __restrict__ x, const float* __restrict__ W1,
       const float* __restrict__ b1) {
    __shared__ float sW[8][68];
    __shared__ float ss[64], sq[64];
    int tid = threadIdx.x;
    for (int idx = tid; idx < 512; idx += 256) sW[idx >> 6][idx & 63] = W1[idx];
    if (tid < 64) { ss[tid] = 0.f; sq[tid] = 0.f; }
    __syncthreads();

    int lane = tid & 31, warp = tid >> 5;
    int sub = lane >> 3, c = lane & 7;
    int n = (blockIdx.x * 8 + warp) * 4 + sub;
    // aggregate feature c of node n
    float d = g_dis[n];
    float a = d * d * x[n * IN_CC + c];
    float b = 0.f;
    int beg = g_off[n], end = beg + g_cnt[n];
    int j = beg;
    for (; j + 2 <= end; j += 2) {
        int2 e0 = g_csr[j], e1 = g_csr[j + 1];
        a += __int_as_float(e0.y) * x[e0.x * IN_CC + c];
        b += __int_as_float(e1.y) * x[e1.x * IN_CC + c];
    }
    if (j < end) {
        int2 e = g_csr[j];
        a += __int_as_float(e.y) * x[e.x * IN_CC + c];
    }
    float agg = a + b;
    // broadcast 8 agg features within the node's lane group, compute 8 output cols
    float av[8];
#pragma unroll
    for (int k = 0; k < 8; k++)
        av[k] = __shfl_sync(0xffffffffu, agg, (lane & ~7) + k);
    int col0 = c * 8;
    float out[8];
#pragma unroll
    for (int jj = 0; jj < 8; jj++) {
        int col = col0 + jj;
        float v = b1[col];
#pragma unroll
        for (int k = 0; k < 8; k++) v += av[k] * sW[k][col];
        v = fmaxf(v, 0.f);
        out[jj] = v;
        g_Xc[(size_t)n * 128 + col] = v;
    }
#pragma unroll
    for (int jj = 0; jj < 8; jj++) {
        atomicAdd(&ss[col0 + jj], out[jj]);
        atomicAdd(&sq[col0 + jj], out[jj] * out[jj]);
    }
    __syncthreads();
    if (tid < 64) {
        atomicAdd(&g_stats[tid], ss[tid]);
        atomicAdd(&g_stats[64 + tid], sq[tid]);
    }
}

// ---------------- gather layer 2 + bias + relu + stats -> Xc[:,64:128] ----------------
__global__ void __launch_bounds__(256)
k_gather2(const float* __restrict__ bias) {
    int warp = threadIdx.x >> 5, lane = threadIdx.x & 31;
    int n0 = (blockIdx.x * 8 + warp) * 8;
    float bc0 = bias[lane], bc1 = bias[lane + 32];
    float s0 = 0.f, q0 = 0.f, s1 = 0.f, q1 = 0.f;
#pragma unroll 1
    for (int k = 0; k < 8; k++) {
        int n = n0 + k;
        float d = g_dis[n];
        float d2 = d * d;
        float a0 = d2 * g_h[(size_t)n * 64 + lane];
        float a1 = d2 * g_h[(size_t)n * 64 + lane + 32];
        float b0 = 0.f, b1 = 0.f;
        int beg = g_off[n], end = beg + g_cnt[n];
        int j = beg;
        for (; j + 4 <= end; j += 4) {
            int2 e0 = g_csr[j],     e1 = g_csr[j + 1];
            int2 e2 = g_csr[j + 2], e3 = g_csr[j + 3];
            float w0 = __int_as_float(e0.y), w1 = __int_as_float(e1.y);
            float w2 = __int_as_float(e2.y), w3 = __int_as_float(e3.y);
            float x00 = g_h[(size_t)e0.x * 64 + lane];
            float x01 = g_h[(size_t)e0.x * 64 + lane + 32];
            float x10 = g_h[(size_t)e1.x * 64 + lane];
            float x11 = g_h[(size_t)e1.x * 64 + lane + 32];
            float x20 = g_h[(size_t)e2.x * 64 + lane];
            float x21 = g_h[(size_t)e2.x * 64 + lane + 32];
            float x30 = g_h[(size_t)e3.x * 64 + lane];
            float x31 = g_h[(size_t)e3.x * 64 + lane + 32];
            a0 += w0 * x00; a1 += w0 * x01;
            b0 += w1 * x10; b1 += w1 * x11;
            a0 += w2 * x20; a1 += w2 * x21;
            b0 += w3 * x30; b1 += w3 * x31;
        }
        for (; j < end; j++) {
            int2 e = g_csr[j];
            float w = __int_as_float(e.y);
            a0 += w * g_h[(size_t)e.x * 64 + lane];
            a1 += w * g_h[(size_t)e.x * 64 + lane + 32];
        }
        float v0 = fmaxf(a0 + b0 + bc0, 0.f);
        float v1 = fmaxf(a1 + b1 + bc1, 0.f);
        g_Xc[(size_t)n * 128 + 64 + lane]      = v0;
        g_Xc[(size_t)n * 128 + 96 + lane]      = v1;
        s0 += v0; q0 += v0 * v0;
        s1 += v1; q1 += v1 * v1;
    }
    __shared__ float ss[64], sq[64];
    if (threadIdx.x < 64) { ss[threadIdx.x] = 0.f; sq[threadIdx.x] = 0.f; }
    __syncthreads();
    atomicAdd(&ss[lane], s0);      atomicAdd(&sq[lane], q0);
    atomicAdd(&ss[lane + 32], s1); atomicAdd(&sq[lane + 32], q1);
    __syncthreads();
    if (threadIdx.x < 64) {
        atomicAdd(&g_stats[threadIdx.x], ss[threadIdx.x]);
        atomicAdd(&g_stats[64 + threadIdx.x], sq[threadIdx.x]);
    }
}

// finalize BN params into g_bnp12 at column offset; self-zero stats
__global__ void k_bnfinal(const float* __restrict__ gam, const float* __restrict__ bet, int off) {
    int c = threadIdx.x;
    if (c < 64) {
        float inv_n = 1.f / (float)N_BIGC;
        float m = g_stats[c] * inv_n;
        float var = g_stats[64 + c] * inv_n - m * m;
        float a = rsqrtf(var + 1e-5f) * gam[c];
        g_bnp12[off + c] = a;
        g_bnp12[128 + off + c] = bet[c] - m * a;
        g_stats[c] = 0.f;
        g_stats[64 + c] = 0.f;
    }
}

// ---------------- tf32 helpers ----------------
__device__ __forceinline__ unsigned f2tf(float f) {
    unsigned u;
    asm("cvt.rna.tf32.f32 %0, %1;" : "=r"(u) : "f"(f));
    return u;
}

#define MMA_TF32(c0,c1,c2,c3,a0,a1,a2,a3,b0,b1)                              \
    asm volatile("mma.sync.aligned.m16n8k8.row.col.f32.tf32.tf32.f32 "       \
                 "{%0,%1,%2,%3}, {%4,%5,%6,%7}, {%8,%9}, {%0,%1,%2,%3};"     \
                 : "+f"(c0), "+f"(c1), "+f"(c2), "+f"(c3)                    \
                 : "r"(a0), "r"(a1), "r"(a2), "r"(a3), "r"(b0), "r"(b1))

// ---------------- tf32 tensor-core GEMM ----------------
// BT=1: B is [N,K] (A@B^T). BT=0: B is [K,N].
// SPLIT=1 (decoder fused mode): N=2*DHC, B col n<DHC from dWa[k][n] (src half),
//   n>=DHC from dWa[DHC+k][n-DHC] (trg half); bias1 only on n<DHC; out fp16 to
//   g_Psh (n<DHC) / g_Pth (n-DHC).
template <int BT, int OH, int SPLIT>
__global__ void __launch_bounds__(256, 2)
k_tf32gemm(const float* __restrict__ A, const float* __restrict__ B,
           const float* __restrict__ bias1, const float* __restrict__ bias2,
           const float* __restrict__ ascale,
           void* __restrict__ Cv, int M, int N, int K,
           int lda, int ldb, int ldc) {
    __shared__ unsigned As[128][33];
    __shared__ unsigned Bs[128][33];
    int tid = threadIdx.x;
    int warp = tid >> 5, lane = tid & 31;
    int wm = warp >> 2, wn = warp & 3;
    int rowBase = blockIdx.y * 128, colBase = blockIdx.x * 128;
    int lr = lane >> 2, lc = lane & 3;

    float c[4][4][4];
#pragma unroll
    for (int mi = 0; mi < 4; mi++)
#pragma unroll
        for (int ni = 0; ni < 4; ni++)
#pragma unroll
            for (int q = 0; q < 4; q++) c[mi][ni][q] = 0.f;

    for (int k0 = 0; k0 < K; k0 += 32) {
#pragma unroll
        for (int q = 0; q < 16; q++) {
            int idx = q * 256 + tid;
            int r = idx >> 5, kk = idx & 31;
            int gr = rowBase + r, gk = k0 + kk;
            float v = (gr < M && gk < K) ? A[(size_t)gr * lda + gk] : 0.f;
            if (ascale) v = fmaf(v, ascale[gk], ascale[128 + gk]);
            As[r][kk] = f2tf(v);
        }
        if (BT) {
#pragma unroll
            for (int q = 0; q < 16; q++) {
                int idx = q * 256 + tid;
                int n = idx >> 5, kk = idx & 31;
                int gn = colBase + n, gk = k0 + kk;
                float v = (gn < N && gk < K) ? B[(size_t)gn * ldb + gk] : 0.f;
                Bs[n][kk] = f2tf(v);
            }
        } else {
#pragma unroll
            for (int q = 0; q < 16; q++) {
                int idx = q * 256 + tid;
                int n = idx & 127, kk = idx >> 7;
                int gn = colBase + n, gk = k0 + kk;
                float v = 0.f;
                if (gn < N && gk < K) {
                    if (SPLIT) {
                        int half = gn >= DHC;
                        int cc = gn - half * DHC;
                        v = B[(size_t)(gk + half * DHC) * ldb + cc];
                    } else {
                        v = B[(size_t)gk * ldb + gn];
                    }
                }
                Bs[n][kk] = f2tf(v);
            }
        }
        __syncthreads();

#pragma unroll
        for (int ks = 0; ks < 4; ks++) {
            int k8 = ks * 8;
            unsigned a[4][4], b[4][2];
#pragma unroll
            for (int mi = 0; mi < 4; mi++) {
                int r0 = wm * 64 + mi * 16 + lr;
                a[mi][0] = As[r0][k8 + lc];
                a[mi][1] = As[r0 + 8][k8 + lc];
                a[mi][2] = As[r0][k8 + lc + 4];
                a[mi][3] = As[r0 + 8][k8 + lc + 4];
            }
#pragma unroll
            for (int ni = 0; ni < 4; ni++) {
                int n0 = wn * 32 + ni * 8 + lr;
                b[ni][0] = Bs[n0][k8 + lc];
                b[ni][1] = Bs[n0][k8 + lc + 4];
            }
#pragma unroll
            for (int mi = 0; mi < 4; mi++)
#pragma unroll
                for (int ni = 0; ni < 4; ni++)
                    MMA_TF32(c[mi][ni][0], c[mi][ni][1], c[mi][ni][2], c[mi][ni][3],
                             a[mi][0], a[mi][1], a[mi][2], a[mi][3],
                             b[ni][0], b[ni][1]);
        }
        __syncthreads();
    }

#pragma unroll
    for (int mi = 0; mi < 4; mi++) {
#pragma unroll
        for (int ni = 0; ni < 4; ni++) {
            int gr0 = rowBase + wm * 64 + mi * 16 + lr;
            int gc0 = colBase + wn * 32 + ni * 8 + lc * 2;
#pragma unroll
            for (int q = 0; q < 4; q++) {
                int gr = gr0 + (q >> 1) * 8;
                int gc = gc0 + (q & 1);
                if (gr < M && gc < N) {
                    float val = c[mi][ni][q];
                    if (SPLIT) {
                        if (gc < DHC) {
                            if (bias1) val += bias1[gc];
                            g_Psh[(size_t)gr * PSTRIDE + gc] = __float2half(val);
                        } else {
                            g_Pth[(size_t)gr * PSTRIDE + (gc - DHC)] = __float2half(val);
                        }
                    } else {
                        if (bias1) val += bias1[gc];
                        if (bias2) val += bias2[gc];
                        if (OH) ((__half*)Cv)[(size_t)gr * ldc + gc] = __float2half(val);
                        else    ((float*)Cv)[(size_t)gr * ldc + gc] = val;
                    }
                }
            }
        }
    }
}

// ---------------- SGEMM N=64 with BN-affine A-load: g_h = BN(A)@B ----------------
__global__ void k_sgemm64_gcn(const float* __restrict__ A, const float* __restrict__ B,
                              const float* __restrict__ bnp, int M, int K, int lda) {
    __shared__ float As[8][132];
    __shared__ float Bs[8][68];
    int tx = threadIdx.x, ty = threadIdx.y;
    int tid = ty * 16 + tx;
    int rowBase = blockIdx.x * 128;
    float acc[8][4];
#pragma unroll
    for (int i = 0; i < 8; i++)
#pragma unroll
        for (int j = 0; j < 4; j++) acc[i][j] = 0.f;

    for (int k0 = 0; k0 < K; k0 += 8) {
#pragma unroll
        for (int q = 0; q < 4; q++) {
            int idx = q * 256 + tid;
            int r = idx >> 3, kk = idx & 7;
            int gr = rowBase + r, gk = k0 + kk;
            float v = (gr < M && gk < K) ? A[(size_t)gr * lda + gk] : 0.f;
            if (bnp) v = fmaf(v, bnp[gk], bnp[128 + gk]);
            As[kk][r] = v;
        }
#pragma unroll
        for (int q = 0; q < 2; q++) {
            int idx = q * 256 + tid;
            int cc = idx & 63, kk = idx >> 6;
            int gk = k0 + kk;
            Bs[kk][cc] = (gk < K) ? B[(size_t)gk * 64 + cc] : 0.f;
        }
        __syncthreads();
#pragma unroll
        for (int kk = 0; kk < 8; kk++) {
            float a[8], b[4];
            *(float4*)(a)     = *(const float4*)&As[kk][ty * 4];
            *(float4*)(a + 4) = *(const float4*)&As[kk][64 + ty * 4];
            *(float4*)(b)     = *(const float4*)&Bs[kk][tx * 4];
#pragma unroll
            for (int i = 0; i < 8; i++)
#pragma unroll
                for (int j = 0; j < 4; j++) acc[i][j] += a[i] * b[j];
        }
        __syncthreads();
    }

#pragma unroll
    for (int i = 0; i < 8; i++) {
        int gr = rowBase + ((i < 4) ? (ty * 4 + i) : (64 + ty * 4 + i - 4));
        if (gr < M) {
#pragma unroll
            for (int j = 0; j < 4; j++) {
                int gc = tx * 4 + j;
                g_h[(size_t)gr * 64 + gc] = acc[i][j];
            }
        }
    }
}

// ---------------- fused LSTM recurrence (4-row chunks, f32x2, fp32 gates) --------------
// hfinal written with row stride ldf (direct into g_emb column block)
__global__ void k_lstm(const float* __restrict__ gates, const float* __restrict__ Whh,
                       float* __restrict__ y, float* __restrict__ hfinal, int ldf,
                       int nrows) {
    extern __shared__ float sm[];
    float* sW = sm;                 // [256][68]
    float* hb = sm + 256 * 68;      // [2][64][68]
    int tx = threadIdx.x, ty = threadIdx.y;
    int tid = ty * 64 + tx;
    for (int idx = tid; idx < 256 * 64; idx += 256) {
        int g = idx >> 6, k = idx & 63;
        sW[g * 68 + k] = Whh[idx];
    }
    for (int idx = tid; idx < 2 * 64 * 68; idx += 256) hb[idx] = 0.f;
    __syncthreads();

    int row0 = blockIdx.x * 64;
    float cst[16];
#pragma unroll
    for (int i = 0; i < 16; i++) cst[i] = 0.f;
    int cur = 0;

    for (int t = 0; t < 8; t++) {
        const float* gt = gates + (size_t)t * nrows * 256;
        const float* hbc = hb + cur * 64 * 68;
        float* hbn = hb + (cur ^ 1) * 64 * 68;
#pragma unroll
        for (int ch = 0; ch < 4; ch++) {
            int lr0 = ty * 16 + ch * 4;
            u64 ai[4], af[4], ag[4], ao[4];
#pragma unroll
            for (int r = 0; r < 4; r++) {
                int grow = row0 + lr0 + r;
                if (grow < nrows) {
                    const float* gp = gt + (size_t)grow * 256;
                    ai[r] = pack2(gp[tx], 0.f);
                    af[r] = pack2(gp[64 + tx], 0.f);
                    ag[r] = pack2(gp[128 + tx], 0.f);
                    ao[r] = pack2(gp[192 + tx], 0.f);
                } else {
                    ai[r] = af[r] = ag[r] = ao[r] = 0ull;
                }
            }
#pragma unroll
            for (int k0 = 0; k0 < 64; k0 += 4) {
                ulonglong2 wi = *(const ulonglong2*)&sW[(size_t)tx * 68 + k0];
                ulonglong2 wf = *(const ulonglong2*)&sW[(size_t)(64 + tx) * 68 + k0];
                ulonglong2 wg = *(const ulonglong2*)&sW[(size_t)(128 + tx) * 68 + k0];
                ulonglong2 wo = *(const ulonglong2*)&sW[(size_t)(192 + tx) * 68 + k0];
#pragma unroll
                for (int r = 0; r < 4; r++) {
                    ulonglong2 h2 = *(const ulonglong2*)&hbc[(size_t)(lr0 + r) * 68 + k0];
                    ai[r] = fma2(h2.x, wi.x, ai[r]); ai[r] = fma2(h2.y, wi.y, ai[r]);
                    af[r] = fma2(h2.x, wf.x, af[r]); af[r] = fma2(h2.y, wf.y, af[r]);
                    ag[r] = fma2(h2.x, wg.x, ag[r]); ag[r] = fma2(h2.y, wg.y, ag[r]);
                    ao[r] = fma2(h2.x, wo.x, ao[r]); ao[r] = fma2(h2.y, wo.y, ao[r]);
                }
            }
#pragma unroll
            for (int r = 0; r < 4; r++) {
                int grow = row0 + lr0 + r;
                float iv = sum2(ai[r]), fv = sum2(af[r]);
                float gv = sum2(ag[r]), ov = sum2(ao[r]);
                float ig = 1.f / (1.f + expf(-iv));
                float fg = 1.f / (1.f + expf(-fv));
                float gg = tanhf(gv);
                float og = 1.f / (1.f + expf(-ov));
                float c = fg * cst[ch * 4 + r] + ig * gg;
                cst[ch * 4 + r] = c;
                float h = og * tanhf(c);
                hbn[(size_t)(lr0 + r) * 68 + tx] = h;
                if (grow < nrows) {
                    if (y) y[((size_t)t * nrows + grow) * 64 + tx] = h;
                    if (t == 7) hfinal[(size_t)grow * ldf + tx] = h;
                }
            }
        }
        cur ^= 1;
        __syncthreads();
    }
}

// ---------------- edge decoder: 2 edges per warp (16 lanes each), half2 tables --------
__global__ void k_edge(const int* __restrict__ ewi, const float* __restrict__ dWb,
                       const float* __restrict__ dbb, float* __restrict__ out) {
    __shared__ float sw[PSTRIDE];
    if (threadIdx.x < PSTRIDE) sw[threadIdx.x] = (threadIdx.x < DHC) ? dWb[threadIdx.x] : 0.f;
    __syncthreads();
    int e = (blockIdx.x * blockDim.x + threadIdx.x) >> 4;   // half-warp = edge
    int l16 = threadIdx.x & 15;
    if (e >= E_DECC) return;
    int s = ewi[e], tg = ewi[E_DECC + e];
    const __half2* ps = (const __half2*)(g_Psh + (size_t)s * PSTRIDE);
    const __half2* pt = (const __half2*)(g_Pth + (size_t)tg * PSTRIDE);
    const float2* sw2 = (const float2*)sw;
    float acc = 0.f;
#pragma unroll
    for (int seg = 0; seg < 5; seg++) {
        int j = l16 + (seg << 4);
        if (seg < 4 || l16 < 8) {           // 72 half2 total
            float2 a = __half22float2(ps[j]);
            float2 b = __half22float2(pt[j]);
            float2 w = sw2[j];
            acc += fmaxf(a.x + b.x, 0.f) * w.x + fmaxf(a.y + b.y, 0.f) * w.y;
        }
    }
#pragma unroll
    for (int o = 8; o; o >>= 1) acc += __shfl_down_sync(0xffffffffu, acc, o, 16);
    if (l16 == 0) out[e] = acc + dbb[0];
}

// ---------------- host ----------------
extern "C" void kernel_launch(void* const* d_in, const int* in_sizes, int n_in,
                              void* d_out, int out_size) {
    const float *x = 0, *ea = 0;
    const int *ei = 0, *ewi = 0;
    const float* w[20] = {0};
    int wi = 0;
    for (int i = 0; i < n_in; i++) {
        int s = in_sizes[i];
        if      (s == N_BIGC * IN_CC) x   = (const float*)d_in[i];
        else if (s == E_MAIN)         ea  = (const float*)d_in[i];
        else if (s == 2 * E_MAIN)     ei  = (const int*)d_in[i];
        else if (s == 2 * E_DECC)     ewi = (const int*)d_in[i];
        else if (wi < 20)             w[wi++] = (const float*)d_in[i];
    }
    const float *W1 = w[0], *b1 = w[1], *g1 = w[2], *be1 = w[3];
    const float *W2 = w[4], *b2 = w[5], *g2 = w[6], *be2 = w[7];
    const float *Wih1 = w[8], *Whh1 = w[9], *bih1 = w[10], *bhh1 = w[11];
    const float *Wih2 = w[12], *Whh2 = w[13], *bih2 = w[14], *bhh2 = w[15];
    const float *dWa = w[16], *dba = w[17], *dWb = w[18], *dbb = w[19];

    float *p_Xc, *p_gates, *p_y1, *p_emb, *p_bnp12;
    cudaGetSymbolAddress((void**)&p_Xc, g_Xc);
    cudaGetSymbolAddress((void**)&p_gates, g_gates);
    cudaGetSymbolAddress((void**)&p_y1, g_y1);
    cudaGetSymbolAddress((void**)&p_emb, g_emb);
    cudaGetSymbolAddress((void**)&p_bnp12, g_bnp12);

    const int lstm_smem = (256 * 68 + 2 * 64 * 68) * 4;  // 104448 B
    cudaFuncSetAttribute(k_lstm, cudaFuncAttributeMaxDynamicSharedMemorySize, lstm_smem);

    // --- graph normalization + CSR build (+ early skip-feature fill) ---
    k_init<<<(N_BIGC + 255) / 256, 256>>>();
    k_embS<<<(N_NODESC * 15 + 255) / 256, 256>>>(x);
    k_degcount<<<(E_MAIN + 255) / 256, 256>>>(ei, ea);
    k_disalloc<<<(N_BIGC + 255) / 256, 256>>>();
    k_fill<<<(E_MAIN + 255) / 256, 256>>>(ei, ea);

    // --- GCN layer 1: fused aggregate + GEMM + relu + stats ---
    k_gcn1<<<N_BIGC / 32, 256>>>(x, W1, b1);
    k_bnfinal<<<1, 64>>>(g1, be1, 0);

    // --- GCN layer 2: GEMM (BN-affine on A) then gather+relu+stats ---
    k_sgemm64_gcn<<<(N_BIGC + 127) / 128, dim3(16, 16)>>>(p_Xc, W2, p_bnp12,
                                                          N_BIGC, HIDC, 2 * HIDC);
    k_gather2<<<N_BIGC / 64, 256>>>(b2);
    k_bnfinal<<<1, 64>>>(g2, be2, 64);

    // --- LSTM 1: tf32 gate GEMM (BN-affine on A) + fused recurrence (H1 -> emb[:,0:64]) ---
    {
        dim3 grid(2, (N_BIGC + 127) / 128);
        k_tf32gemm<1, 0, 0><<<grid, 256>>>(p_Xc, Wih1, bih1, bhh1, p_bnp12, p_gates,
                                           N_BIGC, 4 * HIDC, 2 * HIDC,
                                           2 * HIDC, 2 * HIDC, 4 * HIDC);
        dim3 gl((N_NODESC + 63) / 64), bl(64, 4);
        k_lstm<<<gl, bl, lstm_smem>>>(p_gates, Whh1, p_y1, p_emb, DHC, N_NODESC);
    }

    // --- LSTM 2 (H2 -> emb[:,64:128]) ---
    {
        dim3 grid(2, (N_BIGC + 127) / 128);
        k_tf32gemm<1, 0, 0><<<grid, 256>>>(p_y1, Wih2, bih2, bhh2, 0, p_gates,
                                           N_BIGC, 4 * HIDC, HIDC,
                                           HIDC, HIDC, 4 * HIDC);
        dim3 gl((N_NODESC + 63) / 64), bl(64, 4);
        k_lstm<<<gl, bl, lstm_smem>>>(p_gates, Whh2, 0, p_emb + 64, DHC, N_NODESC);
    }

    // --- fused decoder projections: emb @ [dWa_src | dWa_trg] -> Psh, Pth (fp16) ---
    {
        dim3 grid((2 * DHC + 127) / 128, (N_NODESC + 127) / 128);
        k_tf32gemm<0, 1, 1><<<grid, 256>>>(p_emb, dWa, dba, 0, 0, 0,
                                           N_NODESC, 2 * DHC, DHC, DHC, DHC, 0);
    }

    // --- edge decoder: 2 edges per warp ---
    k_edge<<<(E_DECC * 16 + 255) / 256, 256>>>(ewi, dWb, dbb, (float*)d_out);
}

// round 14
// speedup vs baseline: 1.0653x; 1.0653x over previous
#include <cuda_runtime.h>
#include <cuda_fp16.h>
#include <math.h>

#define N_NODESC 20000
#define WINDOWC  8
#define N_BIGC   160000
#define IN_CC    8
#define HIDC     64
#define E_MAIN   1600000
#define E_DECC   500000
#define DHC      143
#define PSTRIDE  144

typedef unsigned long long u64;

// ---------------- scratch (static device globals; no allocation) ----------------
__device__ float g_dis[N_BIGC];
__device__ float g_aggx[N_BIGC * IN_CC];      // aggregated raw features (layer-1 trick)
__device__ float g_h[N_BIGC * HIDC];          // GCN2 GEMM output
__device__ float g_Xc[N_BIGC * 2 * HIDC];     // pre-BN relu outputs of both layers
__device__ float g_gates[N_BIGC * 4 * HIDC];  // fp32 gate preactivations
__device__ float g_y1[N_BIGC * HIDC];
__device__ float g_emb[N_NODESC * DHC];       // H1 | H2 | S (filled by lstm1/lstm2/embS)
__device__ __half g_Psh[N_NODESC * PSTRIDE];  // col 143 never written -> stays 0
__device__ __half g_Pth[N_NODESC * PSTRIDE];
__device__ float g_stats[128];
__device__ float g_bnp12[256];                // scale[128], shift[128] for Xc columns
// CSR (built once per launch, used by both GCN layers)
__device__ int2  g_csr[E_MAIN];
__device__ int   g_cnt[N_BIGC];
__device__ int   g_off[N_BIGC];
__device__ int   g_cur[N_BIGC];
__device__ int   g_total[1];

// ---------------- packed f32x2 helpers ----------------
__device__ __forceinline__ u64 fma2(u64 a, u64 b, u64 c) {
    u64 d;
    asm("fma.rn.f32x2 %0, %1, %2, %3;" : "=l"(d) : "l"(a), "l"(b), "l"(c));
    return d;
}
__device__ __forceinline__ u64 pack2(float lo, float hi) {
    u64 p;
    asm("mov.b64 %0, {%1, %2};" : "=l"(p) : "f"(lo), "f"(hi));
    return p;
}
__device__ __forceinline__ float sum2(u64 p) {
    float lo, hi;
    asm("mov.b64 {%0, %1}, %2;" : "=f"(lo), "=f"(hi) : "l"(p));
    return lo + hi;
}

// ---------------- init ----------------
__global__ void k_init() {
    int i = blockIdx.x * blockDim.x + threadIdx.x;
    if (i < N_BIGC) { g_dis[i] = 0.f; g_cnt[i] = 0; }
    if (i < 128) g_stats[i] = 0.f;
    if (i == 0) g_total[0] = 0;
}

// skip features S -> emb cols 128..142 (depends only on x; launched early)
__global__ void k_embS(const float* __restrict__ x) {
    int i = blockIdx.x * blockDim.x + threadIdx.x;
    if (i >= N_NODESC * 15) return;
    int b = i / 15, j = i - b * 15;
    float v;
    if (j < 8) v = x[(size_t)b * 8 + j];
    else { int t = j - 7; v = x[((size_t)t * N_NODESC + b) * 8 + 7]; }
    g_emb[(size_t)b * DHC + 128 + j] = v;
}

__global__ void k_degcount(const int* __restrict__ ei, const float* __restrict__ ea) {
    int i = blockIdx.x * blockDim.x + threadIdx.x;
    if (i < E_MAIN) {
        int c = ei[E_MAIN + i];
        atomicAdd(&g_dis[c], ea[i]);
        atomicAdd(&g_cnt[c], 1);
    }
}

__global__ void k_disalloc() {
    int i = blockIdx.x * blockDim.x + threadIdx.x;
    if (i >= N_BIGC) return;
    g_dis[i] = rsqrtf(g_dis[i] + 1.0f);
    int lane = threadIdx.x & 31;
    int c = g_cnt[i];
    int scan = c;
#pragma unroll
    for (int o = 1; o < 32; o <<= 1) {
        int v = __shfl_up_sync(0xffffffffu, scan, o);
        if (lane >= o) scan += v;
    }
    int excl = scan - c;
    int base = 0;
    if (lane == 31) base = atomicAdd(&g_total[0], scan);
    base = __shfl_sync(0xffffffffu, base, 31);
    g_off[i] = base + excl;
    g_cur[i] = base + excl;
}

__global__ void k_fill(const int* __restrict__ ei, const float* __restrict__ ea) {
    int e = blockIdx.x * blockDim.x + threadIdx.x;
    if (e >= E_MAIN) return;
    int r = ei[e], c = ei[E_MAIN + e];
    float w = g_dis[r] * ea[e] * g_dis[c];
    int pos = atomicAdd(&g_cur[c], 1);
    g_csr[pos] = make_int2(r, __float_as_int(w));
}

// ---------------- layer-1 trick: aggregate raw x (8 cols) ----------------
__global__ void __launch_bounds__(256)
k_gatherx(const float* __restrict__ x) {
    int lane = threadIdx.x & 31, warp = threadIdx.x >> 5;
    int sub = lane >> 3, c = lane & 7;
    int n = (blockIdx.x * 8 + warp) * 4 + sub;
    float d = g_dis[n];
    float a = d * d * x[n * IN_CC + c];
    float b = 0.f;
    int beg = g_off[n], end = beg + g_cnt[n];
    int j = beg;
    for (; j + 2 <= end; j += 2) {
        int2 e0 = g_csr[j], e1 = g_csr[j + 1];
        a += __int_as_float(e0.y) * x[e0.x * IN_CC + c];
        b += __int_as_float(e1.y) * x[e1.x * IN_CC + c];
    }
    if (j < end) {
        int2 e = g_csr[j];
        a += __int_as_float(e.y) * x[e.x * IN_CC + c];
    }
    g_aggx[n * IN_CC + c] = a + b;
}

// ---------------- GEMM1: aggx[N,8]@W1[8,64]+b1 -> relu -> stats -> Xc[:,0:64] ----------
__global__ void __launch_bounds__(256)
k_gemm1(const float* __restrict__ W1, const float* __restrict__ b1) {
    __shared__ float sW[8][68];
    int tid = threadIdx.x;
    for (int idx = tid; idx < 512; idx += 256) sW[idx >> 6][idx & 63] = W1[idx];
    __syncthreads();
    int warp = tid >> 5, lane = tid & 31;
    int n0 = (blockIdx.x * 8 + warp) * 8;
    float bc0 = b1[lane], bc1 = b1[lane + 32];
    float s0 = 0.f, q0 = 0.f, s1 = 0.f, q1 = 0.f;
#pragma unroll
    for (int r = 0; r < 8; r++) {
        int n = n0 + r;
        float4 xa = *(const float4*)&g_aggx[n * IN_CC];
        float4 xb = *(const float4*)&g_aggx[n * IN_CC + 4];
        float a0 = bc0, a1 = bc1;
        a0 += xa.x * sW[0][lane] + xa.y * sW[1][lane] + xa.z * sW[2][lane] + xa.w * sW[3][lane]
            + xb.x * sW[4][lane] + xb.y * sW[5][lane] + xb.z * sW[6][lane] + xb.w * sW[7][lane];
        a1 += xa.x * sW[0][lane+32] + xa.y * sW[1][lane+32] + xa.z * sW[2][lane+32] + xa.w * sW[3][lane+32]
            + xb.x * sW[4][lane+32] + xb.y * sW[5][lane+32] + xb.z * sW[6][lane+32] + xb.w * sW[7][lane+32];
        float v0 = fmaxf(a0, 0.f), v1 = fmaxf(a1, 0.f);
        g_Xc[(size_t)n * 128 + lane]      = v0;
        g_Xc[(size_t)n * 128 + lane + 32] = v1;
        s0 += v0; q0 += v0 * v0;
        s1 += v1; q1 += v1 * v1;
    }
    __shared__ float ss[64], sq[64];
    if (tid < 64) { ss[tid] = 0.f; sq[tid] = 0.f; }
    __syncthreads();
    atomicAdd(&ss[lane], s0);      atomicAdd(&sq[lane], q0);
    atomicAdd(&ss[lane + 32], s1); atomicAdd(&sq[lane + 32], q1);
    __syncthreads();
    if (tid < 64) {
        atomicAdd(&g_stats[tid], ss[tid]);
        atomicAdd(&g_stats[64 + tid], sq[tid]);
    }
}

// ---------------- gather layer 2 + bias + relu + stats -> Xc[:,64:128] ----------------
__global__ void __launch_bounds__(256)
k_gather2(const float* __restrict__ bias) {
    int warp = threadIdx.x >> 5, lane = threadIdx.x & 31;
    int n0 = (blockIdx.x * 8 + warp) * 8;
    float bc0 = bias[lane], bc1 = bias[lane + 32];
    float s0 = 0.f, q0 = 0.f, s1 = 0.f, q1 = 0.f;
#pragma unroll 1
    for (int k = 0; k < 8; k++) {
        int n = n0 + k;
        float d = g_dis[n];
        float d2 = d * d;
        float a0 = d2 * g_h[(size_t)n * 64 + lane];
        float a1 = d2 * g_h[(size_t)n * 64 + lane + 32];
        float b0 = 0.f, b1 = 0.f;
        int beg = g_off[n], end = beg + g_cnt[n];
        int j = beg;
        for (; j + 4 <= end; j += 4) {
            int2 e0 = g_csr[j],     e1 = g_csr[j + 1];
            int2 e2 = g_csr[j + 2], e3 = g_csr[j + 3];
            float w0 = __int_as_float(e0.y), w1 = __int_as_float(e1.y);
            float w2 = __int_as_float(e2.y), w3 = __int_as_float(e3.y);
            float x00 = g_h[(size_t)e0.x * 64 + lane];
            float x01 = g_h[(size_t)e0.x * 64 + lane + 32];
            float x10 = g_h[(size_t)e1.x * 64 + lane];
            float x11 = g_h[(size_t)e1.x * 64 + lane + 32];
            float x20 = g_h[(size_t)e2.x * 64 + lane];
            float x21 = g_h[(size_t)e2.x * 64 + lane + 32];
            float x30 = g_h[(size_t)e3.x * 64 + lane];
            float x31 = g_h[(size_t)e3.x * 64 + lane + 32];
            a0 += w0 * x00; a1 += w0 * x01;
            b0 += w1 * x10; b1 += w1 * x11;
            a0 += w2 * x20; a1 += w2 * x21;
            b0 += w3 * x30; b1 += w3 * x31;
        }
        for (; j < end; j++) {
            int2 e = g_csr[j];
            float w = __int_as_float(e.y);
            a0 += w * g_h[(size_t)e.x * 64 + lane];
            a1 += w * g_h[(size_t)e.x * 64 + lane + 32];
        }
        float v0 = fmaxf(a0 + b0 + bc0, 0.f);
        float v1 = fmaxf(a1 + b1 + bc1, 0.f);
        g_Xc[(size_t)n * 128 + 64 + lane]      = v0;
        g_Xc[(size_t)n * 128 + 96 + lane]      = v1;
        s0 += v0; q0 += v0 * v0;
        s1 += v1; q1 += v1 * v1;
    }
    __shared__ float ss[64], sq[64];
    if (threadIdx.x < 64) { ss[threadIdx.x] = 0.f; sq[threadIdx.x] = 0.f; }
    __syncthreads();
    atomicAdd(&ss[lane], s0);      atomicAdd(&sq[lane], q0);
    atomicAdd(&ss[lane + 32], s1); atomicAdd(&sq[lane + 32], q1);
    __syncthreads();
    if (threadIdx.x < 64) {
        atomicAdd(&g_stats[threadIdx.x], ss[threadIdx.x]);
        atomicAdd(&g_stats[64 + threadIdx.x], sq[threadIdx.x]);
    }
}

// finalize BN params into g_bnp12 at column offset; self-zero stats
__global__ void k_bnfinal(const float* __restrict__ gam, const float* __restrict__ bet, int off) {
    int c = threadIdx.x;
    if (c < 64) {
        float inv_n = 1.f / (float)N_BIGC;
        float m = g_stats[c] * inv_n;
        float var = g_stats[64 + c] * inv_n - m * m;
        float a = rsqrtf(var + 1e-5f) * gam[c];
        g_bnp12[off + c] = a;
        g_bnp12[128 + off + c] = bet[c] - m * a;
        g_stats[c] = 0.f;
        g_stats[64 + c] = 0.f;
    }
}

// ---------------- tf32 helpers ----------------
__device__ __forceinline__ unsigned f2tf(float f) {
    unsigned u;
    asm("cvt.rna.tf32.f32 %0, %1;" : "=r"(u) : "f"(f));
    return u;
}

#define MMA_TF32(c0,c1,c2,c3,a0,a1,a2,a3,b0,b1)                              \
    asm volatile("mma.sync.aligned.m16n8k8.row.col.f32.tf32.tf32.f32 "       \
                 "{%0,%1,%2,%3}, {%4,%5,%6,%7}, {%8,%9}, {%0,%1,%2,%3};"     \
                 : "+f"(c0), "+f"(c1), "+f"(c2), "+f"(c3)                    \
                 : "r"(a0), "r"(a1), "r"(a2), "r"(a3), "r"(b0), "r"(b1))

// ---------------- tf32 tensor-core GEMM ----------------
// BT=1: B is [N,K] (A@B^T). BT=0: B is [K,N].
// SPLIT=1: fused decoder; N=2*DHC, B col n<DHC from dWa src half, else trg half;
//   bias1 only on n<DHC; fp16 out to g_Psh / g_Pth.
template <int BT, int OH, int SPLIT>
__global__ void __launch_bounds__(256, 2)
k_tf32gemm(const float* __restrict__ A, const float* __restrict__ B,
           const float* __restrict__ bias1, const float* __restrict__ bias2,
           const float* __restrict__ ascale,
           void* __restrict__ Cv, int M, int N, int K,
           int lda, int ldb, int ldc) {
    __shared__ unsigned As[128][33];
    __shared__ unsigned Bs[128][33];
    int tid = threadIdx.x;
    int warp = tid >> 5, lane = tid & 31;
    int wm = warp >> 2, wn = warp & 3;
    int rowBase = blockIdx.y * 128, colBase = blockIdx.x * 128;
    int lr = lane >> 2, lc = lane & 3;

    float c[4][4][4];
#pragma unroll
    for (int mi = 0; mi < 4; mi++)
#pragma unroll
        for (int ni = 0; ni < 4; ni++)
#pragma unroll
            for (int q = 0; q < 4; q++) c[mi][ni][q] = 0.f;

    for (int k0 = 0; k0 < K; k0 += 32) {
#pragma unroll
        for (int q = 0; q < 16; q++) {
            int idx = q * 256 + tid;
            int r = idx >> 5, kk = idx & 31;
            int gr = rowBase + r, gk = k0 + kk;
            float v = (gr < M && gk < K) ? A[(size_t)gr * lda + gk] : 0.f;
            if (ascale) v = fmaf(v, ascale[gk], ascale[128 + gk]);
            As[r][kk] = f2tf(v);
        }
        if (BT) {
#pragma unroll
            for (int q = 0; q < 16; q++) {
                int idx = q * 256 + tid;
                int n = idx >> 5, kk = idx & 31;
                int gn = colBase + n, gk = k0 + kk;
                float v = (gn < N && gk < K) ? B[(size_t)gn * ldb + gk] : 0.f;
                Bs[n][kk] = f2tf(v);
            }
        } else {
#pragma unroll
            for (int q = 0; q < 16; q++) {
                int idx = q * 256 + tid;
                int n = idx & 127, kk = idx >> 7;
                int gn = colBase + n, gk = k0 + kk;
                float v = 0.f;
                if (gn < N && gk < K) {
                    if (SPLIT) {
                        int half = gn >= DHC;
                        int cc = gn - half * DHC;
                        v = B[(size_t)(gk + half * DHC) * ldb + cc];
                    } else {
                        v = B[(size_t)gk * ldb + gn];
                    }
                }
                Bs[n][kk] = f2tf(v);
            }
        }
        __syncthreads();

#pragma unroll
        for (int ks = 0; ks < 4; ks++) {
            int k8 = ks * 8;
            unsigned a[4][4], b[4][2];
#pragma unroll
            for (int mi = 0; mi < 4; mi++) {
                int r0 = wm * 64 + mi * 16 + lr;
                a[mi][0] = As[r0][k8 + lc];
                a[mi][1] = As[r0 + 8][k8 + lc];
                a[mi][2] = As[r0][k8 + lc + 4];
                a[mi][3] = As[r0 + 8][k8 + lc + 4];
            }
#pragma unroll
            for (int ni = 0; ni < 4; ni++) {
                int n0 = wn * 32 + ni * 8 + lr;
                b[ni][0] = Bs[n0][k8 + lc];
                b[ni][1] = Bs[n0][k8 + lc + 4];
            }
#pragma unroll
            for (int mi = 0; mi < 4; mi++)
#pragma unroll
                for (int ni = 0; ni < 4; ni++)
                    MMA_TF32(c[mi][ni][0], c[mi][ni][1], c[mi][ni][2], c[mi][ni][3],
                             a[mi][0], a[mi][1], a[mi][2], a[mi][3],
                             b[ni][0], b[ni][1]);
        }
        __syncthreads();
    }

#pragma unroll
    for (int mi = 0; mi < 4; mi++) {
#pragma unroll
        for (int ni = 0; ni < 4; ni++) {
            int gr0 = rowBase + wm * 64 + mi * 16 + lr;
            int gc0 = colBase + wn * 32 + ni * 8 + lc * 2;
#pragma unroll
            for (int q = 0; q < 4; q++) {
                int gr = gr0 + (q >> 1) * 8;
                int gc = gc0 + (q & 1);
                if (gr < M && gc < N) {
                    float val = c[mi][ni][q];
                    if (SPLIT) {
                        if (gc < DHC) {
                            if (bias1) val += bias1[gc];
                            g_Psh[(size_t)gr * PSTRIDE + gc] = __float2half(val);
                        } else {
                            g_Pth[(size_t)gr * PSTRIDE + (gc - DHC)] = __float2half(val);
                        }
                    } else {
                        if (bias1) val += bias1[gc];
                        if (bias2) val += bias2[gc];
                        if (OH) ((__half*)Cv)[(size_t)gr * ldc + gc] = __float2half(val);
                        else    ((float*)Cv)[(size_t)gr * ldc + gc] = val;
                    }
                }
            }
        }
    }
}

// ---------------- SGEMM N=64 with BN-affine A-load: g_h = BN(A)@B ----------------
__global__ void k_sgemm64_gcn(const float* __restrict__ A, const float* __restrict__ B,
                              const float* __restrict__ bnp, int M, int K, int lda) {
    __shared__ float As[8][132];
    __shared__ float Bs[8][68];
    int tx = threadIdx.x, ty = threadIdx.y;
    int tid = ty * 16 + tx;
    int rowBase = blockIdx.x * 128;
    float acc[8][4];
#pragma unroll
    for (int i = 0; i < 8; i++)
#pragma unroll
        for (int j = 0; j < 4; j++) acc[i][j] = 0.f;

    for (int k0 = 0; k0 < K; k0 += 8) {
#pragma unroll
        for (int q = 0; q < 4; q++) {
            int idx = q * 256 + tid;
            int r = idx >> 3, kk = idx & 7;
            int gr = rowBase + r, gk = k0 + kk;
            float v = (gr < M && gk < K) ? A[(size_t)gr * lda + gk] : 0.f;
            if (bnp) v = fmaf(v, bnp[gk], bnp[128 + gk]);
            As[kk][r] = v;
        }
#pragma unroll
        for (int q = 0; q < 2; q++) {
            int idx = q * 256 + tid;
            int cc = idx & 63, kk = idx >> 6;
            int gk = k0 + kk;
            Bs[kk][cc] = (gk < K) ? B[(size_t)gk * 64 + cc] : 0.f;
        }
        __syncthreads();
#pragma unroll
        for (int kk = 0; kk < 8; kk++) {
            float a[8], b[4];
            *(float4*)(a)     = *(const float4*)&As[kk][ty * 4];
            *(float4*)(a + 4) = *(const float4*)&As[kk][64 + ty * 4];
            *(float4*)(b)     = *(const float4*)&Bs[kk][tx * 4];
#pragma unroll
            for (int i = 0; i < 8; i++)
#pragma unroll
                for (int j = 0; j < 4; j++) acc[i][j] += a[i] * b[j];
        }
        __syncthreads();
    }

#pragma unroll
    for (int i = 0; i < 8; i++) {
        int gr = rowBase + ((i < 4) ? (ty * 4 + i) : (64 + ty * 4 + i - 4));
        if (gr < M) {
#pragma unroll
            for (int j = 0; j < 4; j++) {
                int gc = tx * 4 + j;
                g_h[(size_t)gr * 64 + gc] = acc[i][j];
            }
        }
    }
}

// ---------------- fused LSTM recurrence (4-row chunks, f32x2, fp32 gates) --------------
// hfinal written with row stride ldf (direct into g_emb column block)
__global__ void k_lstm(const float* __restrict__ gates, const float* __restrict__ Whh,
                       float* __restrict__ y, float* __restrict__ hfinal, int ldf,
                       int nrows) {
    extern __shared__ float sm[];
    float* sW = sm;                 // [256][68]
    float* hb = sm + 256 * 68;      // [2][64][68]
    int tx = threadIdx.x, ty = threadIdx.y;
    int tid = ty * 64 + tx;
    for (int idx = tid; idx < 256 * 64; idx += 256) {
        int g = idx >> 6, k = idx & 63;
        sW[g * 68 + k] = Whh[idx];
    }
    for (int idx = tid; idx < 2 * 64 * 68; idx += 256) hb[idx] = 0.f;
    __syncthreads();

    int row0 = blockIdx.x * 64;
    float cst[16];
#pragma unroll
    for (int i = 0; i < 16; i++) cst[i] = 0.f;
    int cur = 0;

    for (int t = 0; t < 8; t++) {
        const float* gt = gates + (size_t)t * nrows * 256;
        const float* hbc = hb + cur * 64 * 68;
        float* hbn = hb + (cur ^ 1) * 64 * 68;
#pragma unroll
        for (int ch = 0; ch < 4; ch++) {
            int lr0 = ty * 16 + ch * 4;
            u64 ai[4], af[4], ag[4], ao[4];
#pragma unroll
            for (int r = 0; r < 4; r++) {
                int grow = row0 + lr0 + r;
                if (grow < nrows) {
                    const float* gp = gt + (size_t)grow * 256;
                    ai[r] = pack2(gp[tx], 0.f);
                    af[r] = pack2(gp[64 + tx], 0.f);
                    ag[r] = pack2(gp[128 + tx], 0.f);
                    ao[r] = pack2(gp[192 + tx], 0.f);
                } else {
                    ai[r] = af[r] = ag[r] = ao[r] = 0ull;
                }
            }
#pragma unroll
            for (int k0 = 0; k0 < 64; k0 += 4) {
                ulonglong2 wi = *(const ulonglong2*)&sW[(size_t)tx * 68 + k0];
                ulonglong2 wf = *(const ulonglong2*)&sW[(size_t)(64 + tx) * 68 + k0];
                ulonglong2 wg = *(const ulonglong2*)&sW[(size_t)(128 + tx) * 68 + k0];
                ulonglong2 wo = *(const ulonglong2*)&sW[(size_t)(192 + tx) * 68 + k0];
#pragma unroll
                for (int r = 0; r < 4; r++) {
                    ulonglong2 h2 = *(const ulonglong2*)&hbc[(size_t)(lr0 + r) * 68 + k0];
                    ai[r] = fma2(h2.x, wi.x, ai[r]); ai[r] = fma2(h2.y, wi.y, ai[r]);
                    af[r] = fma2(h2.x, wf.x, af[r]); af[r] = fma2(h2.y, wf.y, af[r]);
                    ag[r] = fma2(h2.x, wg.x, ag[r]); ag[r] = fma2(h2.y, wg.y, ag[r]);
                    ao[r] = fma2(h2.x, wo.x, ao[r]); ao[r] = fma2(h2.y, wo.y, ao[r]);
                }
            }
#pragma unroll
            for (int r = 0; r < 4; r++) {
                int grow = row0 + lr0 + r;
                float iv = sum2(ai[r]), fv = sum2(af[r]);
                float gv = sum2(ag[r]), ov = sum2(ao[r]);
                float ig = 1.f / (1.f + expf(-iv));
                float fg = 1.f / (1.f + expf(-fv));
                float gg = tanhf(gv);
                float og = 1.f / (1.f + expf(-ov));
                float c = fg * cst[ch * 4 + r] + ig * gg;
                cst[ch * 4 + r] = c;
                float h = og * tanhf(c);
                hbn[(size_t)(lr0 + r) * 68 + tx] = h;
                if (grow < nrows) {
                    if (y) y[((size_t)t * nrows + grow) * 64 + tx] = h;
                    if (t == 7) hfinal[(size_t)grow * ldf + tx] = h;
                }
            }
        }
        cur ^= 1;
        __syncthreads();
    }
}

// ---------------- edge decoder: 2 edges per warp (16 lanes each), half2 tables --------
__global__ void k_edge(const int* __restrict__ ewi, const float* __restrict__ dWb,
                       const float* __restrict__ dbb, float* __restrict__ out) {
    __shared__ float sw[PSTRIDE];
    if (threadIdx.x < PSTRIDE) sw[threadIdx.x] = (threadIdx.x < DHC) ? dWb[threadIdx.x] : 0.f;
    __syncthreads();
    int e = (blockIdx.x * blockDim.x + threadIdx.x) >> 4;   // half-warp = edge
    int l16 = threadIdx.x & 15;
    if (e >= E_DECC) return;
    int s = ewi[e], tg = ewi[E_DECC + e];
    const __half2* ps = (const __half2*)(g_Psh + (size_t)s * PSTRIDE);
    const __half2* pt = (const __half2*)(g_Pth + (size_t)tg * PSTRIDE);
    const float2* sw2 = (const float2*)sw;
    float acc = 0.f;
#pragma unroll
    for (int seg = 0; seg < 5; seg++) {
        int j = l16 + (seg << 4);
        if (seg < 4 || l16 < 8) {           // 72 half2 total
            float2 a = __half22float2(ps[j]);
            float2 b = __half22float2(pt[j]);
            float2 w = sw2[j];
            acc += fmaxf(a.x + b.x, 0.f) * w.x + fmaxf(a.y + b.y, 0.f) * w.y;
        }
    }
#pragma unroll
    for (int o = 8; o; o >>= 1) acc += __shfl_down_sync(0xffffffffu, acc, o, 16);
    if (l16 == 0) out[e] = acc + dbb[0];
}

// ---------------- host ----------------
extern "C" void kernel_launch(void* const* d_in, const int* in_sizes, int n_in,
                              void* d_out, int out_size) {
    const float *x = 0, *ea = 0;
    const int *ei = 0, *ewi = 0;
    const float* w[20] = {0};
    int wi = 0;
    for (int i = 0; i < n_in; i++) {
        int s = in_sizes[i];
        if      (s == N_BIGC * IN_CC) x   = (const float*)d_in[i];
        else if (s == E_MAIN)         ea  = (const float*)d_in[i];
        else if (s == 2 * E_MAIN)     ei  = (const int*)d_in[i];
        else if (s == 2 * E_DECC)     ewi = (const int*)d_in[i];
        else if (wi < 20)             w[wi++] = (const float*)d_in[i];
    }
    const float *W1 = w[0], *b1 = w[1], *g1 = w[2], *be1 = w[3];
    const float *W2 = w[4], *b2 = w[5], *g2 = w[6], *be2 = w[7];
    const float *Wih1 = w[8], *Whh1 = w[9], *bih1 = w[10], *bhh1 = w[11];
    const float *Wih2 = w[12], *Whh2 = w[13], *bih2 = w[14], *bhh2 = w[15];
    const float *dWa = w[16], *dba = w[17], *dWb = w[18], *dbb = w[19];

    float *p_Xc, *p_gates, *p_y1, *p_emb, *p_bnp12;
    cudaGetSymbolAddress((void**)&p_Xc, g_Xc);
    cudaGetSymbolAddress((void**)&p_gates, g_gates);
    cudaGetSymbolAddress((void**)&p_y1, g_y1);
    cudaGetSymbolAddress((void**)&p_emb, g_emb);
    cudaGetSymbolAddress((void**)&p_bnp12, g_bnp12);

    const int lstm_smem = (256 * 68 + 2 * 64 * 68) * 4;  // 104448 B
    cudaFuncSetAttribute(k_lstm, cudaFuncAttributeMaxDynamicSharedMemorySize, lstm_smem);

    // --- graph normalization + CSR build (+ early skip-feature fill) ---
    k_init<<<(N_BIGC + 255) / 256, 256>>>();
    k_embS<<<(N_NODESC * 15 + 255) / 256, 256>>>(x);
    k_degcount<<<(E_MAIN + 255) / 256, 256>>>(ei, ea);
    k_disalloc<<<(N_BIGC + 255) / 256, 256>>>();
    k_fill<<<(E_MAIN + 255) / 256, 256>>>(ei, ea);

    // --- GCN layer 1: aggregate raw x, then GEMM+relu+stats (R12 proven pair) ---
    k_gatherx<<<N_BIGC / 32, 256>>>(x);
    k_gemm1<<<N_BIGC / 64, 256>>>(W1, b1);
    k_bnfinal<<<1, 64>>>(g1, be1, 0);

    // --- GCN layer 2: GEMM (BN-affine on A) then gather+relu+stats ---
    k_sgemm64_gcn<<<(N_BIGC + 127) / 128, dim3(16, 16)>>>(p_Xc, W2, p_bnp12,
                                                          N_BIGC, HIDC, 2 * HIDC);
    k_gather2<<<N_BIGC / 64, 256>>>(b2);
    k_bnfinal<<<1, 64>>>(g2, be2, 64);

    // --- LSTM 1: gate GEMM + recurrence (H1 -> emb[:,0:64]) ---
    {
        dim3 grid(2, (N_BIGC + 127) / 128);
        k_tf32gemm<1, 0, 0><<<grid, 256>>>(p_Xc, Wih1, bih1, bhh1, p_bnp12, p_gates,
                                           N_BIGC, 4 * HIDC, 2 * HIDC,
                                           2 * HIDC, 2 * HIDC, 4 * HIDC);
        dim3 gl((N_NODESC + 63) / 64), bl(64, 4);
        k_lstm<<<gl, bl, lstm_smem>>>(p_gates, Whh1, p_y1, p_emb, DHC, N_NODESC);
    }

    // --- LSTM 2 (H2 -> emb[:,64:128]) ---
    {
        dim3 grid(2, (N_BIGC + 127) / 128);
        k_tf32gemm<1, 0, 0><<<grid, 256>>>(p_y1, Wih2, bih2, bhh2, 0, p_gates,
                                           N_BIGC, 4 * HIDC, HIDC,
                                           HIDC, HIDC, 4 * HIDC);
        dim3 gl((N_NODESC + 63) / 64), bl(64, 4);
        k_lstm<<<gl, bl, lstm_smem>>>(p_gates, Whh2, 0, p_emb + 64, DHC, N_NODESC);
    }

    // --- fused decoder projections: emb @ [dWa_src | dWa_trg] -> Psh, Pth (fp16) ---
    {
        dim3 grid((2 * DHC + 127) / 128, (N_NODESC + 127) / 128);
        k_tf32gemm<0, 1, 1><<<grid, 256>>>(p_emb, dWa, dba, 0, 0, 0,
                                           N_NODESC, 2 * DHC, DHC, DHC, DHC, 0);
    }

    // --- edge decoder: 2 edges per warp ---
    k_edge<<<(E_DECC * 16 + 255) / 256, 256>>>(ewi, dWb, dbb, (float*)d_out);
}

// round 15
// speedup vs baseline: 1.1597x; 1.0886x over previous
#include <cuda_runtime.h>
#include <cuda_fp16.h>
#include <math.h>

#define N_NODESC 20000
#define WINDOWC  8
#define N_BIGC   160000
#define IN_CC    8
#define HIDC     64
#define E_MAIN   1600000
#define E_DECC   500000
#define DHC      143
#define PSTRIDE  144

typedef unsigned long long u64;

// ---------------- scratch (static device globals; no allocation) ----------------
__device__ float g_dis[N_BIGC];
__device__ float g_aggx[N_BIGC * IN_CC];      // aggregated raw features (layer-1 trick)
__device__ float g_h[N_BIGC * HIDC];          // GCN2 GEMM output
__device__ float g_Xc[N_BIGC * 2 * HIDC];     // pre-BN relu outputs of both layers
__device__ float g_gates[N_BIGC * 4 * HIDC];  // fp32 gate preactivations
__device__ float g_y1[N_BIGC * HIDC];
__device__ float g_h2f[N_NODESC * HIDC];
__device__ float g_emb[N_NODESC * DHC];
__device__ __half g_Psh[N_NODESC * PSTRIDE];  // col 143 never written -> stays 0
__device__ __half g_Pth[N_NODESC * PSTRIDE];
__device__ float g_stats[128];
__device__ float g_bnp12[256];                // scale[128], shift[128] for Xc columns
// CSR (built once per launch, used by both GCN layers)
__device__ int2  g_csr[E_MAIN];
__device__ int   g_cnt[N_BIGC];
__device__ int   g_off[N_BIGC];
__device__ int   g_cur[N_BIGC];
__device__ int   g_total[1];

// ---------------- packed f32x2 helpers ----------------
__device__ __forceinline__ u64 fma2(u64 a, u64 b, u64 c) {
    u64 d;
    asm("fma.rn.f32x2 %0, %1, %2, %3;" : "=l"(d) : "l"(a), "l"(b), "l"(c));
    return d;
}
__device__ __forceinline__ u64 pack2(float lo, float hi) {
    u64 p;
    asm("mov.b64 %0, {%1, %2};" : "=l"(p) : "f"(lo), "f"(hi));
    return p;
}
__device__ __forceinline__ float sum2(u64 p) {
    float lo, hi;
    asm("mov.b64 {%0, %1}, %2;" : "=f"(lo), "=f"(hi) : "l"(p));
    return lo + hi;
}

// ---------------- init ----------------
__global__ void k_init() {
    int i = blockIdx.x * blockDim.x + threadIdx.x;
    if (i < N_BIGC) { g_dis[i] = 0.f; g_cnt[i] = 0; }
    if (i < 128) g_stats[i] = 0.f;
    if (i == 0) g_total[0] = 0;
}

__global__ void k_degcount(const int* __restrict__ ei, const float* __restrict__ ea) {
    int i = blockIdx.x * blockDim.x + threadIdx.x;
    if (i < E_MAIN) {
        int c = ei[E_MAIN + i];
        atomicAdd(&g_dis[c], ea[i]);
        atomicAdd(&g_cnt[c], 1);
    }
}

__global__ void k_disalloc() {
    int i = blockIdx.x * blockDim.x + threadIdx.x;
    if (i >= N_BIGC) return;
    g_dis[i] = rsqrtf(g_dis[i] + 1.0f);
    int lane = threadIdx.x & 31;
    int c = g_cnt[i];
    int scan = c;
#pragma unroll
    for (int o = 1; o < 32; o <<= 1) {
        int v = __shfl_up_sync(0xffffffffu, scan, o);
        if (lane >= o) scan += v;
    }
    int excl = scan - c;
    int base = 0;
    if (lane == 31) base = atomicAdd(&g_total[0], scan);
    base = __shfl_sync(0xffffffffu, base, 31);
    g_off[i] = base + excl;
    g_cur[i] = base + excl;
}

__global__ void k_fill(const int* __restrict__ ei, const float* __restrict__ ea) {
    int e = blockIdx.x * blockDim.x + threadIdx.x;
    if (e >= E_MAIN) return;
    int r = ei[e], c = ei[E_MAIN + e];
    float w = g_dis[r] * ea[e] * g_dis[c];
    int pos = atomicAdd(&g_cur[c], 1);
    g_csr[pos] = make_int2(r, __float_as_int(w));
}

// ---------------- layer-1 trick: aggregate raw x (8 cols) ----------------
__global__ void __launch_bounds__(256)
k_gatherx(const float* __restrict__ x) {
    int lane = threadIdx.x & 31, warp = threadIdx.x >> 5;
    int sub = lane >> 3, c = lane & 7;
    int n = (blockIdx.x * 8 + warp) * 4 + sub;
    float d = g_dis[n];
    float a = d * d * x[n * IN_CC + c];
    float b = 0.f;
    int beg = g_off[n], end = beg + g_cnt[n];
    int j = beg;
    for (; j + 2 <= end; j += 2) {
        int2 e0 = g_csr[j], e1 = g_csr[j + 1];
        a += __int_as_float(e0.y) * x[e0.x * IN_CC + c];
        b += __int_as_float(e1.y) * x[e1.x * IN_CC + c];
    }
    if (j < end) {
        int2 e = g_csr[j];
        a += __int_as_float(e.y) * x[e.x * IN_CC + c];
    }
    g_aggx[n * IN_CC + c] = a + b;
}

// ---------------- GEMM1: aggx[N,8]@W1[8,64]+b1 -> relu -> stats -> Xc[:,0:64] ----------
__global__ void __launch_bounds__(256)
k_gemm1(const float* __restrict__ W1, const float* __restrict__ b1) {
    __shared__ float sW[8][68];
    int tid = threadIdx.x;
    for (int idx = tid; idx < 512; idx += 256) sW[idx >> 6][idx & 63] = W1[idx];
    __syncthreads();
    int warp = tid >> 5, lane = tid & 31;
    int n0 = (blockIdx.x * 8 + warp) * 8;
    float bc0 = b1[lane], bc1 = b1[lane + 32];
    float s0 = 0.f, q0 = 0.f, s1 = 0.f, q1 = 0.f;
#pragma unroll
    for (int r = 0; r < 8; r++) {
        int n = n0 + r;
        float4 xa = *(const float4*)&g_aggx[n * IN_CC];
        float4 xb = *(const float4*)&g_aggx[n * IN_CC + 4];
        float a0 = bc0, a1 = bc1;
        a0 += xa.x * sW[0][lane] + xa.y * sW[1][lane] + xa.z * sW[2][lane] + xa.w * sW[3][lane]
            + xb.x * sW[4][lane] + xb.y * sW[5][lane] + xb.z * sW[6][lane] + xb.w * sW[7][lane];
        a1 += xa.x * sW[0][lane+32] + xa.y * sW[1][lane+32] + xa.z * sW[2][lane+32] + xa.w * sW[3][lane+32]
            + xb.x * sW[4][lane+32] + xb.y * sW[5][lane+32] + xb.z * sW[6][lane+32] + xb.w * sW[7][lane+32];
        float v0 = fmaxf(a0, 0.f), v1 = fmaxf(a1, 0.f);
        g_Xc[(size_t)n * 128 + lane]      = v0;
        g_Xc[(size_t)n * 128 + lane + 32] = v1;
        s0 += v0; q0 += v0 * v0;
        s1 += v1; q1 += v1 * v1;
    }
    __shared__ float ss[64], sq[64];
    if (tid < 64) { ss[tid] = 0.f; sq[tid] = 0.f; }
    __syncthreads();
    atomicAdd(&ss[lane], s0);      atomicAdd(&sq[lane], q0);
    atomicAdd(&ss[lane + 32], s1); atomicAdd(&sq[lane + 32], q1);
    __syncthreads();
    if (tid < 64) {
        atomicAdd(&g_stats[tid], ss[tid]);
        atomicAdd(&g_stats[64 + tid], sq[tid]);
    }
}

// ---------------- gather layer 2 + bias + relu + stats -> Xc[:,64:128] ----------------
__global__ void __launch_bounds__(256)
k_gather2(const float* __restrict__ bias) {
    int warp = threadIdx.x >> 5, lane = threadIdx.x & 31;
    int n0 = (blockIdx.x * 8 + warp) * 8;
    float bc0 = bias[lane], bc1 = bias[lane + 32];
    float s0 = 0.f, q0 = 0.f, s1 = 0.f, q1 = 0.f;
#pragma unroll 1
    for (int k = 0; k < 8; k++) {
        int n = n0 + k;
        float d = g_dis[n];
        float d2 = d * d;
        float a0 = d2 * g_h[(size_t)n * 64 + lane];
        float a1 = d2 * g_h[(size_t)n * 64 + lane + 32];
        float b0 = 0.f, b1 = 0.f;
        int beg = g_off[n], end = beg + g_cnt[n];
        int j = beg;
        for (; j + 4 <= end; j += 4) {
            int2 e0 = g_csr[j],     e1 = g_csr[j + 1];
            int2 e2 = g_csr[j + 2], e3 = g_csr[j + 3];
            float w0 = __int_as_float(e0.y), w1 = __int_as_float(e1.y);
            float w2 = __int_as_float(e2.y), w3 = __int_as_float(e3.y);
            float x00 = g_h[(size_t)e0.x * 64 + lane];
            float x01 = g_h[(size_t)e0.x * 64 + lane + 32];
            float x10 = g_h[(size_t)e1.x * 64 + lane];
            float x11 = g_h[(size_t)e1.x * 64 + lane + 32];
            float x20 = g_h[(size_t)e2.x * 64 + lane];
            float x21 = g_h[(size_t)e2.x * 64 + lane + 32];
            float x30 = g_h[(size_t)e3.x * 64 + lane];
            float x31 = g_h[(size_t)e3.x * 64 + lane + 32];
            a0 += w0 * x00; a1 += w0 * x01;
            b0 += w1 * x10; b1 += w1 * x11;
            a0 += w2 * x20; a1 += w2 * x21;
            b0 += w3 * x30; b1 += w3 * x31;
        }
        for (; j < end; j++) {
            int2 e = g_csr[j];
            float w = __int_as_float(e.y);
            a0 += w * g_h[(size_t)e.x * 64 + lane];
            a1 += w * g_h[(size_t)e.x * 64 + lane + 32];
        }
        float v0 = fmaxf(a0 + b0 + bc0, 0.f);
        float v1 = fmaxf(a1 + b1 + bc1, 0.f);
        g_Xc[(size_t)n * 128 + 64 + lane]      = v0;
        g_Xc[(size_t)n * 128 + 96 + lane]      = v1;
        s0 += v0; q0 += v0 * v0;
        s1 += v1; q1 += v1 * v1;
    }
    __shared__ float ss[64], sq[64];
    if (threadIdx.x < 64) { ss[threadIdx.x] = 0.f; sq[threadIdx.x] = 0.f; }
    __syncthreads();
    atomicAdd(&ss[lane], s0);      atomicAdd(&sq[lane], q0);
    atomicAdd(&ss[lane + 32], s1); atomicAdd(&sq[lane + 32], q1);
    __syncthreads();
    if (threadIdx.x < 64) {
        atomicAdd(&g_stats[threadIdx.x], ss[threadIdx.x]);
        atomicAdd(&g_stats[64 + threadIdx.x], sq[threadIdx.x]);
    }
}

// finalize BN params into g_bnp12 at column offset; self-zero stats
__global__ void k_bnfinal(const float* __restrict__ gam, const float* __restrict__ bet, int off) {
    int c = threadIdx.x;
    if (c < 64) {
        float inv_n = 1.f / (float)N_BIGC;
        float m = g_stats[c] * inv_n;
        float var = g_stats[64 + c] * inv_n - m * m;
        float a = rsqrtf(var + 1e-5f) * gam[c];
        g_bnp12[off + c] = a;
        g_bnp12[128 + off + c] = bet[c] - m * a;
        g_stats[c] = 0.f;
        g_stats[64 + c] = 0.f;
    }
}

// ---------------- tf32 helpers ----------------
__device__ __forceinline__ unsigned f2tf(float f) {
    unsigned u;
    asm("cvt.rna.tf32.f32 %0, %1;" : "=r"(u) : "f"(f));
    return u;
}

#define MMA_TF32(c0,c1,c2,c3,a0,a1,a2,a3,b0,b1)                              \
    asm volatile("mma.sync.aligned.m16n8k8.row.col.f32.tf32.tf32.f32 "       \
                 "{%0,%1,%2,%3}, {%4,%5,%6,%7}, {%8,%9}, {%0,%1,%2,%3};"     \
                 : "+f"(c0), "+f"(c1), "+f"(c2), "+f"(c3)                    \
                 : "r"(a0), "r"(a1), "r"(a2), "r"(a3), "r"(b0), "r"(b1))

// ---------------- tf32 tensor-core GEMM ----------------
// BT=1: B is [N,K] (A@B^T). BT=0: B is [K,N].
// DUAL=1: decoder pair in one launch. grid.x=4: half = blockIdx.x>>1 selects
//   weight half (B + half*DHC*ldb) and output table (Psh/Pth); colBase from
//   blockIdx.x&1. Per-tile behavior identical to two separate R12 launches.
template <int BT, int OH, int DUAL>
__global__ void __launch_bounds__(256, 2)
k_tf32gemm(const float* __restrict__ A, const float* __restrict__ B,
           const float* __restrict__ bias1, const float* __restrict__ bias2,
           const float* __restrict__ ascale,
           void* __restrict__ Cv, int M, int N, int K,
           int lda, int ldb, int ldc) {
    __shared__ unsigned As[128][33];
    __shared__ unsigned Bs[128][33];
    int tid = threadIdx.x;
    int warp = tid >> 5, lane = tid & 31;
    int wm = warp >> 2, wn = warp & 3;
    int half = 0, colBase, rowBase = blockIdx.y * 128;
    if (DUAL) {
        half = blockIdx.x >> 1;
        colBase = (blockIdx.x & 1) * 128;
        B += (size_t)half * DHC * ldb;
        if (half) bias1 = 0;
    } else {
        colBase = blockIdx.x * 128;
    }
    int lr = lane >> 2, lc = lane & 3;

    float c[4][4][4];
#pragma unroll
    for (int mi = 0; mi < 4; mi++)
#pragma unroll
        for (int ni = 0; ni < 4; ni++)
#pragma unroll
            for (int q = 0; q < 4; q++) c[mi][ni][q] = 0.f;

    for (int k0 = 0; k0 < K; k0 += 32) {
#pragma unroll
        for (int q = 0; q < 16; q++) {
            int idx = q * 256 + tid;
            int r = idx >> 5, kk = idx & 31;
            int gr = rowBase + r, gk = k0 + kk;
            float v = (gr < M && gk < K) ? A[(size_t)gr * lda + gk] : 0.f;
            if (ascale) v = fmaf(v, ascale[gk], ascale[128 + gk]);
            As[r][kk] = f2tf(v);
        }
        if (BT) {
#pragma unroll
            for (int q = 0; q < 16; q++) {
                int idx = q * 256 + tid;
                int n = idx >> 5, kk = idx & 31;
                int gn = colBase + n, gk = k0 + kk;
                float v = (gn < N && gk < K) ? B[(size_t)gn * ldb + gk] : 0.f;
                Bs[n][kk] = f2tf(v);
            }
        } else {
#pragma unroll
            for (int q = 0; q < 16; q++) {
                int idx = q * 256 + tid;
                int n = idx & 127, kk = idx >> 7;
                int gn = colBase + n, gk = k0 + kk;
                float v = (gn < N && gk < K) ? B[(size_t)gk * ldb + gn] : 0.f;
                Bs[n][kk] = f2tf(v);
            }
        }
        __syncthreads();

#pragma unroll
        for (int ks = 0; ks < 4; ks++) {
            int k8 = ks * 8;
            unsigned a[4][4], b[4][2];
#pragma unroll
            for (int mi = 0; mi < 4; mi++) {
                int r0 = wm * 64 + mi * 16 + lr;
                a[mi][0] = As[r0][k8 + lc];
                a[mi][1] = As[r0 + 8][k8 + lc];
                a[mi][2] = As[r0][k8 + lc + 4];
                a[mi][3] = As[r0 + 8][k8 + lc + 4];
            }
#pragma unroll
            for (int ni = 0; ni < 4; ni++) {
                int n0 = wn * 32 + ni * 8 + lr;
                b[ni][0] = Bs[n0][k8 + lc];
                b[ni][1] = Bs[n0][k8 + lc + 4];
            }
#pragma unroll
            for (int mi = 0; mi < 4; mi++)
#pragma unroll
                for (int ni = 0; ni < 4; ni++)
                    MMA_TF32(c[mi][ni][0], c[mi][ni][1], c[mi][ni][2], c[mi][ni][3],
                             a[mi][0], a[mi][1], a[mi][2], a[mi][3],
                             b[ni][0], b[ni][1]);
        }
        __syncthreads();
    }

    __half* Ch = DUAL ? (half ? g_Pth : g_Psh) : (__half*)Cv;
#pragma unroll
    for (int mi = 0; mi < 4; mi++) {
#pragma unroll
        for (int ni = 0; ni < 4; ni++) {
            int gr0 = rowBase + wm * 64 + mi * 16 + lr;
            int gc0 = colBase + wn * 32 + ni * 8 + lc * 2;
#pragma unroll
            for (int q = 0; q < 4; q++) {
                int gr = gr0 + (q >> 1) * 8;
                int gc = gc0 + (q & 1);
                if (gr < M && gc < N) {
                    float val = c[mi][ni][q];
                    if (bias1) val += bias1[gc];
                    if (bias2) val += bias2[gc];
                    if (OH || DUAL) Ch[(size_t)gr * ldc + gc] = __float2half(val);
                    else            ((float*)Cv)[(size_t)gr * ldc + gc] = val;
                }
            }
        }
    }
}

// ---------------- SGEMM N=64 with BN-affine A-load: g_h = BN(A)@B ----------------
__global__ void k_sgemm64_gcn(const float* __restrict__ A, const float* __restrict__ B,
                              const float* __restrict__ bnp, int M, int K, int lda) {
    __shared__ float As[8][132];
    __shared__ float Bs[8][68];
    int tx = threadIdx.x, ty = threadIdx.y;
    int tid = ty * 16 + tx;
    int rowBase = blockIdx.x * 128;
    float acc[8][4];
#pragma unroll
    for (int i = 0; i < 8; i++)
#pragma unroll
        for (int j = 0; j < 4; j++) acc[i][j] = 0.f;

    for (int k0 = 0; k0 < K; k0 += 8) {
#pragma unroll
        for (int q = 0; q < 4; q++) {
            int idx = q * 256 + tid;
            int r = idx >> 3, kk = idx & 7;
            int gr = rowBase + r, gk = k0 + kk;
            float v = (gr < M && gk < K) ? A[(size_t)gr * lda + gk] : 0.f;
            if (bnp) v = fmaf(v, bnp[gk], bnp[128 + gk]);
            As[kk][r] = v;
        }
#pragma unroll
        for (int q = 0; q < 2; q++) {
            int idx = q * 256 + tid;
            int cc = idx & 63, kk = idx >> 6;
            int gk = k0 + kk;
            Bs[kk][cc] = (gk < K) ? B[(size_t)gk * 64 + cc] : 0.f;
        }
        __syncthreads();
#pragma unroll
        for (int kk = 0; kk < 8; kk++) {
            float a[8], b[4];
            *(float4*)(a)     = *(const float4*)&As[kk][ty * 4];
            *(float4*)(a + 4) = *(const float4*)&As[kk][64 + ty * 4];
            *(float4*)(b)     = *(const float4*)&Bs[kk][tx * 4];
#pragma unroll
            for (int i = 0; i < 8; i++)
#pragma unroll
                for (int j = 0; j < 4; j++) acc[i][j] += a[i] * b[j];
        }
        __syncthreads();
    }

#pragma unroll
    for (int i = 0; i < 8; i++) {
        int gr = rowBase + ((i < 4) ? (ty * 4 + i) : (64 + ty * 4 + i - 4));
        if (gr < M) {
#pragma unroll
            for (int j = 0; j < 4; j++) {
                int gc = tx * 4 + j;
                g_h[(size_t)gr * 64 + gc] = acc[i][j];
            }
        }
    }
}

// ---------------- fused LSTM recurrence (4-row chunks, f32x2, fp32 gates) ----------------
__global__ void k_lstm(const float* __restrict__ gates, const float* __restrict__ Whh,
                       float* __restrict__ y, float* __restrict__ hfinal, int nrows) {
    extern __shared__ float sm[];
    float* sW = sm;                 // [256][68]
    float* hb = sm + 256 * 68;      // [2][64][68]
    int tx = threadIdx.x, ty = threadIdx.y;
    int tid = ty * 64 + tx;
    for (int idx = tid; idx < 256 * 64; idx += 256) {
        int g = idx >> 6, k = idx & 63;
        sW[g * 68 + k] = Whh[idx];
    }
    for (int idx = tid; idx < 2 * 64 * 68; idx += 256) hb[idx] = 0.f;
    __syncthreads();

    int row0 = blockIdx.x * 64;
    float cst[16];
#pragma unroll
    for (int i = 0; i < 16; i++) cst[i] = 0.f;
    int cur = 0;

    for (int t = 0; t < 8; t++) {
        const float* gt = gates + (size_t)t * nrows * 256;
        const float* hbc = hb + cur * 64 * 68;
        float* hbn = hb + (cur ^ 1) * 64 * 68;
#pragma unroll
        for (int ch = 0; ch < 4; ch++) {
            int lr0 = ty * 16 + ch * 4;
            u64 ai[4], af[4], ag[4], ao[4];
#pragma unroll
            for (int r = 0; r < 4; r++) {
                int grow = row0 + lr0 + r;
                if (grow < nrows) {
                    const float* gp = gt + (size_t)grow * 256;
                    ai[r] = pack2(gp[tx], 0.f);
                    af[r] = pack2(gp[64 + tx], 0.f);
                    ag[r] = pack2(gp[128 + tx], 0.f);
                    ao[r] = pack2(gp[192 + tx], 0.f);
                } else {
                    ai[r] = af[r] = ag[r] = ao[r] = 0ull;
                }
            }
#pragma unroll
            for (int k0 = 0; k0 < 64; k0 += 4) {
                ulonglong2 wi = *(const ulonglong2*)&sW[(size_t)tx * 68 + k0];
                ulonglong2 wf = *(const ulonglong2*)&sW[(size_t)(64 + tx) * 68 + k0];
                ulonglong2 wg = *(const ulonglong2*)&sW[(size_t)(128 + tx) * 68 + k0];
                ulonglong2 wo = *(const ulonglong2*)&sW[(size_t)(192 + tx) * 68 + k0];
#pragma unroll
                for (int r = 0; r < 4; r++) {
                    ulonglong2 h2 = *(const ulonglong2*)&hbc[(size_t)(lr0 + r) * 68 + k0];
                    ai[r] = fma2(h2.x, wi.x, ai[r]); ai[r] = fma2(h2.y, wi.y, ai[r]);
                    af[r] = fma2(h2.x, wf.x, af[r]); af[r] = fma2(h2.y, wf.y, af[r]);
                    ag[r] = fma2(h2.x, wg.x, ag[r]); ag[r] = fma2(h2.y, wg.y, ag[r]);
                    ao[r] = fma2(h2.x, wo.x, ao[r]); ao[r] = fma2(h2.y, wo.y, ao[r]);
                }
            }
#pragma unroll
            for (int r = 0; r < 4; r++) {
                int grow = row0 + lr0 + r;
                float iv = sum2(ai[r]), fv = sum2(af[r]);
                float gv = sum2(ag[r]), ov = sum2(ao[r]);
                float ig = 1.f / (1.f + expf(-iv));
                float fg = 1.f / (1.f + expf(-fv));
                float gg = tanhf(gv);
                float og = 1.f / (1.f + expf(-ov));
                float c = fg * cst[ch * 4 + r] + ig * gg;
                cst[ch * 4 + r] = c;
                float h = og * tanhf(c);
                hbn[(size_t)(lr0 + r) * 68 + tx] = h;
                if (grow < nrows) {
                    if (y) y[((size_t)t * nrows + grow) * 64 + tx] = h;
                    if (t == 7 && hfinal) hfinal[(size_t)grow * 64 + tx] = h;
                }
            }
        }
        cur ^= 1;
        __syncthreads();
    }
}

// ---------------- node embedding assembly ----------------
__global__ void k_emb(const float* __restrict__ x) {
    int i = blockIdx.x * blockDim.x + threadIdx.x;
    if (i >= N_NODESC * DHC) return;
    int b = i / DHC, j = i - b * DHC;
    float v;
    if (j < 64)       v = g_y1[((size_t)7 * N_NODESC + b) * 64 + j];
    else if (j < 128) v = g_h2f[(size_t)b * 64 + (j - 64)];
    else if (j < 136) v = x[(size_t)b * 8 + (j - 128)];
    else { int t = j - 135; v = x[((size_t)t * N_NODESC + b) * 8 + 7]; }
    g_emb[i] = v;
}

// ---------------- edge decoder: 2 edges per warp (16 lanes each), half2 tables --------
__global__ void k_edge(const int* __restrict__ ewi, const float* __restrict__ dWb,
                       const float* __restrict__ dbb, float* __restrict__ out) {
    __shared__ float sw[PSTRIDE];
    if (threadIdx.x < PSTRIDE) sw[threadIdx.x] = (threadIdx.x < DHC) ? dWb[threadIdx.x] : 0.f;
    __syncthreads();
    int e = (blockIdx.x * blockDim.x + threadIdx.x) >> 4;   // half-warp = edge
    int l16 = threadIdx.x & 15;
    if (e >= E_DECC) return;
    int s = ewi[e], tg = ewi[E_DECC + e];
    const __half2* ps = (const __half2*)(g_Psh + (size_t)s * PSTRIDE);
    const __half2* pt = (const __half2*)(g_Pth + (size_t)tg * PSTRIDE);
    const float2* sw2 = (const float2*)sw;
    float acc = 0.f;
#pragma unroll
    for (int seg = 0; seg < 5; seg++) {
        int j = l16 + (seg << 4);
        if (seg < 4 || l16 < 8) {           // 72 half2 total
            float2 a = __half22float2(ps[j]);
            float2 b = __half22float2(pt[j]);
            float2 w = sw2[j];
            acc += fmaxf(a.x + b.x, 0.f) * w.x + fmaxf(a.y + b.y, 0.f) * w.y;
        }
    }
#pragma unroll
    for (int o = 8; o; o >>= 1) acc += __shfl_down_sync(0xffffffffu, acc, o, 16);
    if (l16 == 0) out[e] = acc + dbb[0];
}

// ---------------- host ----------------
extern "C" void kernel_launch(void* const* d_in, const int* in_sizes, int n_in,
                              void* d_out, int out_size) {
    const float *x = 0, *ea = 0;
    const int *ei = 0, *ewi = 0;
    const float* w[20] = {0};
    int wi = 0;
    for (int i = 0; i < n_in; i++) {
        int s = in_sizes[i];
        if      (s == N_BIGC * IN_CC) x   = (const float*)d_in[i];
        else if (s == E_MAIN)         ea  = (const float*)d_in[i];
        else if (s == 2 * E_MAIN)     ei  = (const int*)d_in[i];
        else if (s == 2 * E_DECC)     ewi = (const int*)d_in[i];
        else if (wi < 20)             w[wi++] = (const float*)d_in[i];
    }
    const float *W1 = w[0], *b1 = w[1], *g1 = w[2], *be1 = w[3];
    const float *W2 = w[4], *b2 = w[5], *g2 = w[6], *be2 = w[7];
    const float *Wih1 = w[8], *Whh1 = w[9], *bih1 = w[10], *bhh1 = w[11];
    const float *Wih2 = w[12], *Whh2 = w[13], *bih2 = w[14], *bhh2 = w[15];
    const float *dWa = w[16], *dba = w[17], *dWb = w[18], *dbb = w[19];

    float *p_Xc, *p_gates, *p_y1, *p_h2f, *p_emb, *p_bnp12;
    cudaGetSymbolAddress((void**)&p_Xc, g_Xc);
    cudaGetSymbolAddress((void**)&p_gates, g_gates);
    cudaGetSymbolAddress((void**)&p_y1, g_y1);
    cudaGetSymbolAddress((void**)&p_h2f, g_h2f);
    cudaGetSymbolAddress((void**)&p_emb, g_emb);
    cudaGetSymbolAddress((void**)&p_bnp12, g_bnp12);

    const int lstm_smem = (256 * 68 + 2 * 64 * 68) * 4;  // 104448 B
    cudaFuncSetAttribute(k_lstm, cudaFuncAttributeMaxDynamicSharedMemorySize, lstm_smem);

    // --- graph normalization + CSR build ---
    k_init<<<(N_BIGC + 255) / 256, 256>>>();
    k_degcount<<<(E_MAIN + 255) / 256, 256>>>(ei, ea);
    k_disalloc<<<(N_BIGC + 255) / 256, 256>>>();
    k_fill<<<(E_MAIN + 255) / 256, 256>>>(ei, ea);

    // --- GCN layer 1: aggregate raw x, then GEMM+relu+stats ---
    k_gatherx<<<N_BIGC / 32, 256>>>(x);
    k_gemm1<<<N_BIGC / 64, 256>>>(W1, b1);
    k_bnfinal<<<1, 64>>>(g1, be1, 0);

    // --- GCN layer 2: GEMM (BN-affine on A) then gather+relu+stats ---
    k_sgemm64_gcn<<<(N_BIGC + 127) / 128, dim3(16, 16)>>>(p_Xc, W2, p_bnp12,
                                                          N_BIGC, HIDC, 2 * HIDC);
    k_gather2<<<N_BIGC / 64, 256>>>(b2);
    k_bnfinal<<<1, 64>>>(g2, be2, 64);

    // --- LSTM 1: tf32 gate GEMM (BN-affine on A) + fused recurrence ---
    {
        dim3 grid(2, (N_BIGC + 127) / 128);
        k_tf32gemm<1, 0, 0><<<grid, 256>>>(p_Xc, Wih1, bih1, bhh1, p_bnp12, p_gates,
                                           N_BIGC, 4 * HIDC, 2 * HIDC,
                                           2 * HIDC, 2 * HIDC, 4 * HIDC);
        dim3 gl((N_NODESC + 63) / 64), bl(64, 4);
        k_lstm<<<gl, bl, lstm_smem>>>(p_gates, Whh1, p_y1, 0, N_NODESC);
    }

    // --- LSTM 2 ---
    {
        dim3 grid(2, (N_BIGC + 127) / 128);
        k_tf32gemm<1, 0, 0><<<grid, 256>>>(p_y1, Wih2, bih2, bhh2, 0, p_gates,
                                           N_BIGC, 4 * HIDC, HIDC,
                                           HIDC, HIDC, 4 * HIDC);
        dim3 gl((N_NODESC + 63) / 64), bl(64, 4);
        k_lstm<<<gl, bl, lstm_smem>>>(p_gates, Whh2, 0, p_h2f, N_NODESC);
    }

    // --- node embedding + fused dual decoder projection (one launch) ---
    k_emb<<<(N_NODESC * DHC + 255) / 256, 256>>>(x);
    {
        dim3 grid(4, (N_NODESC + 127) / 128);
        k_tf32gemm<0, 1, 1><<<grid, 256>>>(p_emb, dWa, dba, 0, 0, 0,
                                           N_NODESC, DHC, DHC, DHC, DHC, PSTRIDE);
    }

    // --- edge decoder: 2 edges per warp ---
    k_edge<<<(E_DECC * 16 + 255) / 256, 256>>>(ewi, dWb, dbb, (float*)d_out);
}